// round 9
// baseline (speedup 1.0000x reference)
#include <cuda_runtime.h>
#include <cstdint>
#include <math.h>

#define HH 128
#define NPIX 16384
#define PI_F 3.14159265358979f

typedef unsigned long long ull;

// Packed f32x2 ops (sm_100+; FFMA2 reachable only via PTX)
#define MULX2(d,a,b)   asm("mul.rn.f32x2 %0,%1,%2;"    : "=l"(d) : "l"(a), "l"(b))
#define ADDX2(d,a,b)   asm("add.rn.f32x2 %0,%1,%2;"    : "=l"(d) : "l"(a), "l"(b))
#define FMAX2(d,a,b,c) asm("fma.rn.f32x2 %0,%1,%2,%3;" : "=l"(d) : "l"(a), "l"(b), "l"(c))
#define PACK2(d,lo,hi) asm("mov.b64 %0,{%1,%2};"       : "=l"(d) : "f"(lo), "f"(hi))
#define UNPACK2(lo,hi,a) asm("mov.b64 {%0,%1},%2;"     : "=f"(lo), "=f"(hi) : "l"(a))

// Batch-independent per-pixel angle table (filled by init kernel each launch).
__device__ float g_theta[NPIX];

__global__ void init_theta_kernel() {
    int idx = blockIdx.x * blockDim.x + threadIdx.x;
    if (idx < NPIX) {
        float fi = (float)(idx >> 7) - 64.0f;   // xx - cx
        float fj = (float)(idx & 127) - 64.0f;  // yy - cy
        g_theta[idx] = atan2f(fj, fi);
    }
}

__device__ __forceinline__ float fast_sqrt(float x) {
    float r;
    asm("sqrt.approx.f32 %0, %1;" : "=f"(r) : "f"(x));
    return r;
}

__device__ __forceinline__ void cp16(float* dst_smem, const float* src) {
    unsigned int a = (unsigned int)__cvta_generic_to_shared(dst_smem);
    asm volatile("cp.async.cg.shared.global [%0], [%1], 16;" :: "r"(a), "l"(src) : "memory");
}
#define CP_COMMIT() asm volatile("cp.async.commit_group;" ::: "memory")

#define CLUSTER_SYNC() do { \
    asm volatile("barrier.cluster.arrive.aligned;" ::: "memory"); \
    asm volatile("barrier.cluster.wait.aligned;" ::: "memory"); \
} while (0)

__global__ void __launch_bounds__(256, 4) __cluster_dims__(2, 1, 1) decode_kernel(
    const float* __restrict__ W,
    const float* __restrict__ ng,
    const float* __restrict__ nu,
    float* __restrict__ out)
{
    __shared__ float img_s[8192];                    // 64 rows x 128 cols
    __shared__ float s_nbuf[2][2][1024];             // cp.async ring [buf][ng/nu]
    __shared__ alignas(16) float s_C[4][256];        // 0.5*sin(kd*(x+m)), shifted replicas
    __shared__ float s_sinx[128];
    __shared__ float s_yacc[128];
    __shared__ float s_g1[128];
    __shared__ float s_mi[128];
    __shared__ float s_red[24];

    const int b    = blockIdx.x >> 1;
    const int rank = blockIdx.x & 1;
    const int base = rank << 6;
    const int t = threadIdx.x;
    const int t4 = t << 2;

    const size_t gbase = (size_t)b * NPIX;
    const float* ngc = ng + gbase + (base << 7);
    const float* nuc = nu + gbase + (base << 7);

    // ---- prologue: launch noise pipeline stages 0,1 ----
    cp16(&s_nbuf[0][0][t4], ngc + t4);
    cp16(&s_nbuf[0][1][t4], nuc + t4);
    CP_COMMIT();
    cp16(&s_nbuf[1][0][t4], ngc + 1024 + t4);
    cp16(&s_nbuf[1][1][t4], nuc + 1024 + t4);
    CP_COMMIT();

    const float* Wb = W + b * 16;
    float w0  = __ldg(Wb + 0),  w1  = __ldg(Wb + 1),  w2  = __ldg(Wb + 2),  w3  = __ldg(Wb + 3);
    float w4  = __ldg(Wb + 4),  w5  = __ldg(Wb + 5),  w6  = __ldg(Wb + 6),  w7  = __ldg(Wb + 7);
    float w8  = __ldg(Wb + 8),  w9  = __ldg(Wb + 9),  w10 = __ldg(Wb + 10), w11 = __ldg(Wb + 11);
    float w12 = __ldg(Wb + 12), w13 = __ldg(Wb + 13), w14 = __ldg(Wb + 14), w15 = __ldg(Wb + 15);

    // ---- per-image params ----
    const float c0  = w0 * 6.0f;
    float hf = floorf(fminf(fmaxf(__fadd_rn(__fmul_rn(fabsf(w1), 8.0f), 2.0f), 2.0f), 12.0f));
    const int lo_ = 64 - (int)hf;
    const int hi_ = 64 + (int)hf;
    const float kx = w2 * (2.0f * PI_F / 128.0f);
    const float ky = w3 * (2.0f * PI_F / 128.0f);
    const float kd = w4 * (PI_F / 256.0f);
    const float a5 = w5 * 10.0f;
    const float off = truncf(w7 * 5.0f);
    const float bxf = 64.0f + off;                 // bx == by
    const float sigma = 4.0f + fabsf(w7) * 5.0f;
    const float ninv = -0.5f / (sigma * sigma);
    const float rw8 = w8 * 10.0f;
    const float cb = floorf(fminf(fmaxf(__fadd_rn(__fmul_rn(fabsf(w9), 8.0f), 2.0f), 2.0f), 16.0f));
    const float invcb = 1.0f / cb;
    const float angle = w10 * PI_F;
    float sa, ca;
    sincosf(angle, &sa, &ca);
    const float k11 = w11 * 4.0f;
    const float k12 = 0.2f * w12;
    const float k13 = 0.2f * w13;

    // ---- fill 1-D tables ----
    if (t < 128) {
        float tt = (float)t;
        s_sinx[t] = 0.5f * sinf(kx * tt);
        float db = tt - bxf;
        s_g1[t] = expf(db * db * ninv);
        int ip = (int)floorf((tt + 0.5f) * invcb);  // == floor(t/cb) for integer t, integer cb
        s_mi[t] = (ip & 1) ? 0.15f : -0.15f;        // -0.15 * p_i
        s_yacc[t] = 0.5f * sinf(ky * tt)
                  + 0.5f * sinf((tt + a5) * (PI_F / 128.0f))
                  + w6
                  - 0.5f * k13
                  + 0.15f;                           // checkerboard constant folded in
    }
    // diag table: 4 shifted replicas so reads become aligned LDS.128
    {
        float tt = (float)t;
        float sdt, cdt, s1, c1;
        sincosf(kd * tt, &sdt, &cdt);
        sincosf(kd, &s1, &c1);
        float sm = 0.0f, cm = 1.0f;                  // sin/cos(kd*m)
#pragma unroll
        for (int m = 0; m < 4; ++m) {
            s_C[m][t] = 0.5f * (sdt * cm + cdt * sm);
            float sm_n = sm * c1 + cm * s1;
            float cm_n = cm * c1 - sm * s1;
            sm = sm_n; cm = cm_n;
        }
    }
    __syncthreads();

    // ---- per-thread j-quad constants (packed f32x2 pairs) ----
    const int j0 = (t & 31) * 4;
    const float dyf = (float)(j0 - 64);
    float yaccl[4], gyl[4], pjl[4], sqh[4];
#pragma unroll
    for (int l = 0; l < 4; ++l) {
        int jl = j0 + l;
        yaccl[l] = s_yacc[jl];
        gyl[l]  = s_g1[jl];
        int ipj = (int)floorf(((float)jl + 0.5f) * invcb);
        pjl[l]  = (ipj & 1) ? -1.0f : 1.0f;
        sqh[l]  = (jl >= lo_ && jl < hi_) ? 0.5f : 0.0f;
    }
    ull Y01, Y23, G01, G23, PJ01, PJ23, SQ01, SQ23, K11P, K12P, K13P;
    PACK2(Y01, yaccl[0], yaccl[1]);  PACK2(Y23, yaccl[2], yaccl[3]);
    PACK2(G01, gyl[0],  gyl[1]);     PACK2(G23, gyl[2],  gyl[3]);
    PACK2(PJ01, pjl[0], pjl[1]);     PACK2(PJ23, pjl[2], pjl[3]);
    PACK2(SQ01, sqh[0], sqh[1]);     PACK2(SQ23, sqh[2], sqh[3]);
    PACK2(K11P, k11, k11);
    PACK2(K12P, k12, k12);
    PACK2(K13P, k13, k13);

    const int r0 = t >> 5;
    const int pg0 = ((base + r0) << 7) + j0;
    const float* thp = g_theta + pg0;
    float* op = out + gbase + pg0;

    const float SQRT10 = 3.16227766016838f;

    float mnv = __int_as_float(0x7f800000);
    float mxv = __int_as_float(0xff800000);

    // theta prefetch (L2-resident), loaded pre-packed
    ulonglong2 th2 = *(const ulonglong2*)(thp);

    // ---- pass 1 ----
#pragma unroll
    for (int k = 0; k < 8; ++k) {
        if (k < 7) asm volatile("cp.async.wait_group 1;" ::: "memory");
        else       asm volatile("cp.async.wait_group 0;" ::: "memory");

        const ulonglong2 g2 = *(const ulonglong2*)&s_nbuf[k & 1][0][t4];
        const ulonglong2 u2 = *(const ulonglong2*)&s_nbuf[k & 1][1][t4];

        if (k < 6) {
            const int qn = (k + 2) << 10;
            cp16(&s_nbuf[k & 1][0][t4], ngc + qn + t4);
            cp16(&s_nbuf[k & 1][1][t4], nuc + qn + t4);
            CP_COMMIT();
        }

        const ulonglong2 tc2 = th2;
        if (k < 7) th2 = *(const ulonglong2*)(thp + ((k + 1) << 10));

        const int i = base + r0 + (k << 3);
        const float dx = (float)i - 64.0f;
        const float dx2 = dx * dx;
        const float sinxi = s_sinx[i];
        const float g1i = s_g1[i];
        const float mi_i = s_mi[i];
        const float xm = (i >= lo_ && i < hi_) ? 1.0f : 0.0f;
        const float cadx = ca * dx;

        // diag: aligned conflict-free 128-bit LDS from shifted replica (i&3)
        const char* dp = (const char*)s_C + (((i & 3) << 10) + ((i & ~3) << 2));
        const ulonglong2 D2 = *(const ulonglong2*)(dp + (j0 << 2));

        ull g1i_p, mi_p, xm_p;
        PACK2(g1i_p, g1i, g1i);
        PACK2(mi_p, mi_i, mi_i);
        PACK2(xm_p, xm, xm);

        float v[4];
#pragma unroll
        for (int h = 0; h < 2; ++h) {
            const ull Dh  = h ? D2.y  : D2.x;
            const ull Gh  = h ? G23   : G01;
            const ull PJh = h ? PJ23  : PJ01;
            const ull SQh = h ? SQ23  : SQ01;
            const ull Yh  = h ? Y23   : Y01;
            const ull gh  = h ? g2.y  : g2.x;
            const ull uh  = h ? u2.y  : u2.x;
            const ull th  = h ? tc2.y : tc2.x;

            ull P;
            ADDX2(P, Yh, Dh);                 // yacc base + diagonal sinusoid
            FMAX2(P, g1i_p, Gh, P);           // gaussian (separable)
            FMAX2(P, mi_p, PJh, P);           // checkerboard
            FMAX2(P, xm_p, SQh, P);           // central square
            FMAX2(P, gh, K12P, P);            // gaussian noise
            FMAX2(P, uh, K13P, P);            // uniform noise

            ull THp; MULX2(THp, th, K11P);
            float th0, th1; UNPACK2(th0, th1, THp);

            float sacc[2];
#pragma unroll
            for (int l = 0; l < 2; ++l) {
                const float dl = dyf + (float)(h * 2 + l);
                const float r = fast_sqrt(fmaf(dl, dl, dx2));
                float s = sinxi + __saturatef(c0 - r);                 // x-sinusoid + disk
                if (fabsf(r - rw8) < SQRT10) s += 1.0f;                // ring
                if (fabsf(fmaf(sa, dl, cadx)) < 3.0f) s += 0.6f;       // rotated line
                s = fmaf(0.5f, __sinf(l ? th1 : th0), s);              // angular sinusoid
                sacc[l] = s;
            }
            ull S; PACK2(S, sacc[0], sacc[1]);
            ADDX2(P, P, S);
            UNPACK2(v[h * 2], v[h * 2 + 1], P);
        }

        mnv = fminf(mnv, fminf(fminf(v[0], v[1]), fminf(v[2], v[3])));
        mxv = fmaxf(mxv, fmaxf(fmaxf(v[0], v[1]), fmaxf(v[2], v[3])));
        *(float4*)(img_s + ((r0 + (k << 3)) << 7) + j0) = make_float4(v[0], v[1], v[2], v[3]);
    }

    // ---- local (half-image) min/max reduction ----
#pragma unroll
    for (int o = 16; o; o >>= 1) {
        mnv = fminf(mnv, __shfl_xor_sync(0xffffffffu, mnv, o));
        mxv = fmaxf(mxv, __shfl_xor_sync(0xffffffffu, mxv, o));
    }
    if ((t & 31) == 0) {
        s_red[t >> 5] = mnv;
        s_red[8 + (t >> 5)] = mxv;
    }
    __syncthreads();
    if (t == 0) {
        float gmn = s_red[0], gmx = s_red[8];
#pragma unroll
        for (int wdx = 1; wdx < 8; ++wdx) {
            gmn = fminf(gmn, s_red[wdx]);
            gmx = fmaxf(gmx, s_red[8 + wdx]);
        }
        s_red[16] = gmn;
        s_red[17] = gmx;
    }

    // ---- cluster exchange: combine halves ----
    CLUSTER_SYNC();
    if (t == 0) {
        unsigned int laddr = (unsigned int)__cvta_generic_to_shared(&s_red[16]);
        unsigned int paddr;
        unsigned int peer = (unsigned int)(rank ^ 1);
        asm("mapa.shared::cluster.u32 %0, %1, %2;" : "=r"(paddr) : "r"(laddr), "r"(peer));
        float pmn, pmx;
        asm("ld.shared::cluster.f32 %0, [%1];"   : "=f"(pmn) : "r"(paddr));
        asm("ld.shared::cluster.f32 %0, [%1+4];" : "=f"(pmx) : "r"(paddr));
        float gmn = fminf(s_red[16], pmn);
        float gmx = fmaxf(s_red[17], pmx);
        float c = 1.0f + w14;
        float pp = (w15 > 0.0f) ? -c : c;
        float ap = fabsf(pp);
        float denom = (gmx - gmn) + 1e-8f / ap;    // ap==0 -> inf -> A=0 -> out=0 (matches ref)
        float A = ((pp > 0.0f) ? 1.0f : -1.0f) / denom;
        float x0 = (pp > 0.0f) ? gmn : gmx;
        s_red[18] = A;
        s_red[19] = x0;
    }
    CLUSTER_SYNC();

    const float A = s_red[18];
    const float C = -s_red[19] * A;

    // ---- pass 2: normalize from smem, store final ----
#pragma unroll 4
    for (int k = 0; k < 8; ++k) {
        const int q = k << 10;
        float4 vv = *(const float4*)(img_s + ((r0 + (k << 3)) << 7) + j0);
        vv.x = fmaf(vv.x, A, C);
        vv.y = fmaf(vv.y, A, C);
        vv.z = fmaf(vv.z, A, C);
        vv.w = fmaf(vv.w, A, C);
        *(float4*)(op + q) = vv;
    }
}

extern "C" void kernel_launch(void* const* d_in, const int* in_sizes, int n_in,
                              void* d_out, int out_size) {
    const float* W  = (const float*)d_in[0];   // (2048, 16)
    const float* ng = (const float*)d_in[1];   // (2048, 128, 128)
    const float* nu = (const float*)d_in[2];   // (2048, 128, 128)
    float* out = (float*)d_out;                // (2048, 1, 128, 128)

    (void)in_sizes; (void)n_in; (void)out_size;

    init_theta_kernel<<<NPIX / 256, 256>>>();
    decode_kernel<<<4096, 256>>>(W, ng, nu, out);
}

// round 10
// speedup vs baseline: 1.2499x; 1.2499x over previous
#include <cuda_runtime.h>
#include <cstdint>
#include <math.h>

#define HH 128
#define NPIX 16384
#define PI_F 3.14159265358979f

// Batch-independent per-pixel angle table (filled by init kernel each launch).
__device__ float g_theta[NPIX];

__global__ void init_theta_kernel() {
    int idx = blockIdx.x * blockDim.x + threadIdx.x;
    if (idx < NPIX) {
        float fi = (float)(idx >> 7) - 64.0f;   // xx - cx
        float fj = (float)(idx & 127) - 64.0f;  // yy - cy
        g_theta[idx] = atan2f(fj, fi);
    }
}

__device__ __forceinline__ float fast_sqrt(float x) {
    float r;
    asm("sqrt.approx.f32 %0, %1;" : "=f"(r) : "f"(x));
    return r;
}

__device__ __forceinline__ void cp16(float* dst_smem, const float* src) {
    unsigned int a = (unsigned int)__cvta_generic_to_shared(dst_smem);
    asm volatile("cp.async.cg.shared.global [%0], [%1], 16;" :: "r"(a), "l"(src) : "memory");
}
#define CP_COMMIT() asm volatile("cp.async.commit_group;" ::: "memory")

#define CLUSTER_SYNC() do { \
    asm volatile("barrier.cluster.arrive.aligned;" ::: "memory"); \
    asm volatile("barrier.cluster.wait.aligned;" ::: "memory"); \
} while (0)

// R8 structure (best: 82.0us) + one change: diagonal-sinusoid table stored as
// 4 shifted replicas so each quad reads ONE aligned conflict-free LDS.128
// instead of 4 scalar LDS with a 4-way bank conflict.
__global__ void __launch_bounds__(256, 4) __cluster_dims__(2, 1, 1) decode_kernel(
    const float* __restrict__ W,
    const float* __restrict__ ng,
    const float* __restrict__ nu,
    float* __restrict__ out)
{
    __shared__ float img_s[8192];           // 64 rows x 128 cols
    __shared__ float s_nbuf[2][2][1024];    // [stage buf][0=ng,1=nu][8 rows x 128]
    __shared__ alignas(16) float s_C[4][256];  // 0.5*sin(kd*(x+m)), shifted replicas
    __shared__ float s_sinx[128];
    __shared__ float s_yacc[128];
    __shared__ float s_g1[128];
    __shared__ float s_mi[128];
    __shared__ float s_pr[128];
    __shared__ float s_red[24];

    const int b    = blockIdx.x >> 1;
    const int rank = blockIdx.x & 1;
    const int base = rank << 6;          // first row of this CTA's half
    const int t = threadIdx.x;
    const int t4 = t << 2;               // this thread's float offset within a stage

    const size_t gbase = (size_t)b * NPIX;
    const float* ngc = ng + gbase + (base << 7);   // CTA-half base
    const float* nuc = nu + gbase + (base << 7);

    // ---- prologue: start stages 0 and 1 of the noise pipeline immediately ----
    cp16(&s_nbuf[0][0][t4], ngc + t4);
    cp16(&s_nbuf[0][1][t4], nuc + t4);
    CP_COMMIT();
    cp16(&s_nbuf[1][0][t4], ngc + 1024 + t4);
    cp16(&s_nbuf[1][1][t4], nuc + 1024 + t4);
    CP_COMMIT();

    const float* Wb = W + b * 16;
    float w0  = __ldg(Wb + 0),  w1  = __ldg(Wb + 1),  w2  = __ldg(Wb + 2),  w3  = __ldg(Wb + 3);
    float w4  = __ldg(Wb + 4),  w5  = __ldg(Wb + 5),  w6  = __ldg(Wb + 6),  w7  = __ldg(Wb + 7);
    float w8  = __ldg(Wb + 8),  w9  = __ldg(Wb + 9),  w10 = __ldg(Wb + 10), w11 = __ldg(Wb + 11);
    float w12 = __ldg(Wb + 12), w13 = __ldg(Wb + 13), w14 = __ldg(Wb + 14), w15 = __ldg(Wb + 15);

    // ---- per-image params ----
    const float c0  = w0 * 6.0f;
    float hf = floorf(fminf(fmaxf(__fadd_rn(__fmul_rn(fabsf(w1), 8.0f), 2.0f), 2.0f), 12.0f));
    const int lo_ = 64 - (int)hf;
    const int hi_ = 64 + (int)hf;
    const float kx = w2 * (2.0f * PI_F / 128.0f);
    const float ky = w3 * (2.0f * PI_F / 128.0f);
    const float kd = w4 * (PI_F / 256.0f);
    const float a5 = w5 * 10.0f;
    const float off = truncf(w7 * 5.0f);
    const float bxf = 64.0f + off;                 // bx == by
    const float sigma = 4.0f + fabsf(w7) * 5.0f;
    const float ninv = -0.5f / (sigma * sigma);
    const float rw8 = w8 * 10.0f;
    const float cb = floorf(fminf(fmaxf(__fadd_rn(__fmul_rn(fabsf(w9), 8.0f), 2.0f), 2.0f), 16.0f));
    const float invcb = 1.0f / cb;
    const float angle = w10 * PI_F;
    float sa, ca;
    sincosf(angle, &sa, &ca);
    const float k11 = w11 * 4.0f;
    const float k12 = 0.2f * w12;
    const float k13 = 0.2f * w13;

    // ---- fill 1-D tables ----
    if (t < 128) {
        float tt = (float)t;
        s_sinx[t] = 0.5f * sinf(kx * tt);
        float db = tt - bxf;
        s_g1[t] = expf(db * db * ninv);
        int ip = (int)floorf((tt + 0.5f) * invcb);  // == floor(t/cb) for integer t, integer cb
        s_mi[t] = (ip & 1) ? 0.15f : -0.15f;        // -0.15 * p_i
        s_pr[t] = (ip & 1) ? -1.0f : 1.0f;          // p_j
        s_yacc[t] = 0.5f * sinf(ky * tt)
                  + 0.5f * sinf((tt + a5) * (PI_F / 128.0f))
                  + w6
                  - 0.5f * k13
                  + 0.15f;                           // checkerboard constant folded in
    }
    // diag table: 4 shifted replicas -> aligned conflict-free LDS.128 reads
    {
        float tt = (float)t;
        float sdt, cdt, s1, c1;
        sincosf(kd * tt, &sdt, &cdt);
        sincosf(kd, &s1, &c1);
        float sm = 0.0f, cm = 1.0f;                  // sin/cos(kd*m)
#pragma unroll
        for (int m = 0; m < 4; ++m) {
            s_C[m][t] = 0.5f * (sdt * cm + cdt * sm);
            float sm_n = sm * c1 + cm * s1;
            float cm_n = cm * c1 - sm * s1;
            sm = sm_n; cm = cm_n;
        }
    }
    __syncthreads();

    // ---- per-thread j-quad constants ----
    const int j0 = (t & 31) * 4;
    const float dyf = (float)(j0 - 64);
    float yaccl[4], gyl[4], sqh[4], pjl[4];
#pragma unroll
    for (int l = 0; l < 4; ++l) {
        int jl = j0 + l;
        yaccl[l] = s_yacc[jl];
        gyl[l]  = s_g1[jl];
        pjl[l]  = s_pr[jl];
        sqh[l]  = (jl >= lo_ && jl < hi_) ? 0.5f : 0.0f;
    }

    const int r0 = t >> 5;                       // warp id = local row within 8-row group
    const int pg0 = ((base + r0) << 7) + j0;     // first global pixel for this thread
    const float* thp = g_theta + pg0;
    float* op = out + gbase + pg0;

    const float SQRT10 = 3.16227766016838f;

    float mnv = __int_as_float(0x7f800000);
    float mxv = __int_as_float(0xff800000);

    // theta prefetch (L2-resident table)
    float4 th4 = *(const float4*)(thp);

    // ---- pass 1: compute 64 rows into smem, cp.async-pipelined noise ----
#pragma unroll
    for (int k = 0; k < 8; ++k) {
        // wait for stage k (leave the newer in-flight group pending)
        if (k < 7) asm volatile("cp.async.wait_group 1;" ::: "memory");
        else       asm volatile("cp.async.wait_group 0;" ::: "memory");

        // consume my 16B of each stage buffer
        const float4 g4 = *(const float4*)&s_nbuf[k & 1][0][t4];
        const float4 u4 = *(const float4*)&s_nbuf[k & 1][1][t4];

        // refill this buffer with stage k+2
        if (k < 6) {
            const int qn = (k + 2) << 10;
            cp16(&s_nbuf[k & 1][0][t4], ngc + qn + t4);
            cp16(&s_nbuf[k & 1][1][t4], nuc + qn + t4);
            CP_COMMIT();
        }

        const float4 tc = th4;
        if (k < 7) th4 = *(const float4*)(thp + ((k + 1) << 10));

        const int i = base + r0 + (k << 3);      // global row
        const float dx = (float)i - 64.0f;
        const float dx2 = dx * dx;
        const float sinxi = s_sinx[i];
        const float g1i = s_g1[i];
        const float mi_i = s_mi[i];
        const float xm = (i >= lo_ && i < hi_) ? 1.0f : 0.0f;
        const float cadx = ca * dx;

        // diagonal sinusoid quad: one aligned, conflict-free LDS.128
        const float4 d4 = *(const float4*)(&s_C[i & 3][(i & ~3) + j0]);

        float gq[4] = {g4.x, g4.y, g4.z, g4.w};
        float uq[4] = {u4.x, u4.y, u4.z, u4.w};
        float thq[4] = {tc.x, tc.y, tc.z, tc.w};
        float dq[4] = {d4.x, d4.y, d4.z, d4.w};
        float v[4];
#pragma unroll
        for (int l = 0; l < 4; ++l) {
            const float dl = dyf + (float)l;
            float r = fast_sqrt(fmaf(dl, dl, dx2));
            float val = yaccl[l] + __saturatef(c0 - r);            // disk
            val = fmaf(xm, sqh[l], val);                           // central square
            val += sinxi;                                          // x-sinusoid
            val += dq[l];                                          // diagonal sinusoid
            val = fmaf(g1i, gyl[l], val);                          // gaussian (separable)
            if (fabsf(r - rw8) < SQRT10) val += 1.0f;              // ring
            val = fmaf(mi_i, pjl[l], val);                         // checkerboard
            if (fabsf(fmaf(sa, dl, cadx)) < 3.0f) val += 0.6f;     // rotated line
            val = fmaf(0.5f, __sinf(thq[l] * k11), val);           // angular sinusoid
            val = fmaf(gq[l], k12, val);                           // gaussian noise
            val = fmaf(uq[l], k13, val);                           // uniform noise
            v[l] = val;
        }
        mnv = fminf(mnv, fminf(fminf(v[0], v[1]), fminf(v[2], v[3])));
        mxv = fmaxf(mxv, fmaxf(fmaxf(v[0], v[1]), fmaxf(v[2], v[3])));
        *(float4*)(img_s + ((r0 + (k << 3)) << 7) + j0) = make_float4(v[0], v[1], v[2], v[3]);
    }

    // ---- local (half-image) min/max reduction ----
#pragma unroll
    for (int o = 16; o; o >>= 1) {
        mnv = fminf(mnv, __shfl_xor_sync(0xffffffffu, mnv, o));
        mxv = fmaxf(mxv, __shfl_xor_sync(0xffffffffu, mxv, o));
    }
    if ((t & 31) == 0) {
        s_red[t >> 5] = mnv;
        s_red[8 + (t >> 5)] = mxv;
    }
    __syncthreads();
    if (t == 0) {
        float gmn = s_red[0], gmx = s_red[8];
#pragma unroll
        for (int wdx = 1; wdx < 8; ++wdx) {
            gmn = fminf(gmn, s_red[wdx]);
            gmx = fmaxf(gmx, s_red[8 + wdx]);
        }
        s_red[16] = gmn;
        s_red[17] = gmx;
    }

    // ---- cluster exchange: combine halves ----
    CLUSTER_SYNC();   // release s_red[16..17] to peer; all cluster threads arrive
    if (t == 0) {
        unsigned int laddr = (unsigned int)__cvta_generic_to_shared(&s_red[16]);
        unsigned int paddr;
        unsigned int peer = (unsigned int)(rank ^ 1);
        asm("mapa.shared::cluster.u32 %0, %1, %2;" : "=r"(paddr) : "r"(laddr), "r"(peer));
        float pmn, pmx;
        asm("ld.shared::cluster.f32 %0, [%1];"   : "=f"(pmn) : "r"(paddr));
        asm("ld.shared::cluster.f32 %0, [%1+4];" : "=f"(pmx) : "r"(paddr));
        float gmn = fminf(s_red[16], pmn);
        float gmx = fmaxf(s_red[17], pmx);
        // fold contrast, inversion, min/max normalization into out = (x - x0) * A
        float c = 1.0f + w14;
        float pp = (w15 > 0.0f) ? -c : c;
        float ap = fabsf(pp);
        float denom = (gmx - gmn) + 1e-8f / ap;    // ap==0 -> inf -> A=0 -> out=0 (matches ref)
        float A = ((pp > 0.0f) ? 1.0f : -1.0f) / denom;
        float x0 = (pp > 0.0f) ? gmn : gmx;
        s_red[18] = A;
        s_red[19] = x0;
    }
    CLUSTER_SYNC();   // peer done reading our [16,17]; our threads see [18,19]

    const float A = s_red[18];
    const float C = -s_red[19] * A;

    // ---- pass 2: normalize from smem, store final ----
#pragma unroll 4
    for (int k = 0; k < 8; ++k) {
        const int q = k << 10;
        float4 vv = *(const float4*)(img_s + ((r0 + (k << 3)) << 7) + j0);
        vv.x = fmaf(vv.x, A, C);
        vv.y = fmaf(vv.y, A, C);
        vv.z = fmaf(vv.z, A, C);
        vv.w = fmaf(vv.w, A, C);
        *(float4*)(op + q) = vv;
    }
}

extern "C" void kernel_launch(void* const* d_in, const int* in_sizes, int n_in,
                              void* d_out, int out_size) {
    const float* W  = (const float*)d_in[0];   // (2048, 16)
    const float* ng = (const float*)d_in[1];   // (2048, 128, 128)
    const float* nu = (const float*)d_in[2];   // (2048, 128, 128)
    float* out = (float*)d_out;                // (2048, 1, 128, 128)

    (void)in_sizes; (void)n_in; (void)out_size;

    init_theta_kernel<<<NPIX / 256, 256>>>();
    decode_kernel<<<4096, 256>>>(W, ng, nu, out);
}

// round 11
// speedup vs baseline: 1.3954x; 1.1164x over previous
#include <cuda_runtime.h>
#include <cstdint>
#include <math.h>

#define HH 128
#define NPIX 16384
#define PI_F 3.14159265358979f

// Batch-independent per-pixel angle table (filled by init kernel each launch).
__device__ float g_theta[NPIX];

__global__ void init_theta_kernel() {
    int idx = blockIdx.x * blockDim.x + threadIdx.x;
    if (idx < NPIX) {
        float fi = (float)(idx >> 7) - 64.0f;   // xx - cx
        float fj = (float)(idx & 127) - 64.0f;  // yy - cy
        g_theta[idx] = atan2f(fj, fi);
    }
}

__device__ __forceinline__ float fast_sqrt(float x) {
    float r;
    asm("sqrt.approx.f32 %0, %1;" : "=f"(r) : "f"(x));
    return r;
}

__device__ __forceinline__ void cp16(float* dst_smem, const float* src) {
    unsigned int a = (unsigned int)__cvta_generic_to_shared(dst_smem);
    asm volatile("cp.async.cg.shared.global [%0], [%1], 16;" :: "r"(a), "l"(src) : "memory");
}
#define CP_COMMIT() asm volatile("cp.async.commit_group;" ::: "memory")

#define CLUSTER_SYNC() do { \
    asm volatile("barrier.cluster.arrive.aligned;" ::: "memory"); \
    asm volatile("barrier.cluster.wait.aligned;" ::: "memory"); \
} while (0)

// R8 structure + theta staged through cp.async INTO img_s itself:
// for thread t, the pass-1 read/write offset equals t*4 + k*1024 == the cp.async
// fill mapping, and img block k is first touched at iteration k. So theta stage k
// lands in img block k, is read (LDS), then overwritten by the computed pixel --
// per-thread RAW in program order, no extra smem, no barriers, and the last
// per-iteration LDG scoreboard dependency disappears.
__global__ void __launch_bounds__(256, 4) __cluster_dims__(2, 1, 1) decode_kernel(
    const float* __restrict__ W,
    const float* __restrict__ ng,
    const float* __restrict__ nu,
    float* __restrict__ out)
{
    __shared__ float img_s[8192];           // 64 rows x 128 cols (doubles as theta landing)
    __shared__ float s_nbuf[2][2][1024];    // [stage buf][0=ng,1=nu][8 rows x 128]
    __shared__ float s_sinx[128];
    __shared__ float s_yacc[128];
    __shared__ float s_g1[128];
    __shared__ float s_mi[128];
    __shared__ float s_pr[128];
    __shared__ float s_sind[256];
    __shared__ float s_red[24];

    const int b    = blockIdx.x >> 1;
    const int rank = blockIdx.x & 1;
    const int base = rank << 6;          // first row of this CTA's half
    const int t = threadIdx.x;
    const int t4 = t << 2;               // this thread's float offset within a stage

    const size_t gbase = (size_t)b * NPIX;
    const float* ngc = ng + gbase + (base << 7);   // CTA-half base
    const float* nuc = nu + gbase + (base << 7);
    const float* thc = g_theta + (base << 7);

    // ---- prologue: start stages 0 and 1 of the pipeline immediately ----
    cp16(&s_nbuf[0][0][t4], ngc + t4);
    cp16(&s_nbuf[0][1][t4], nuc + t4);
    cp16(&img_s[t4],        thc + t4);          // theta stage 0 -> img block 0
    CP_COMMIT();
    cp16(&s_nbuf[1][0][t4], ngc + 1024 + t4);
    cp16(&s_nbuf[1][1][t4], nuc + 1024 + t4);
    cp16(&img_s[1024 + t4], thc + 1024 + t4);   // theta stage 1 -> img block 1
    CP_COMMIT();

    const float* Wb = W + b * 16;
    float w0  = __ldg(Wb + 0),  w1  = __ldg(Wb + 1),  w2  = __ldg(Wb + 2),  w3  = __ldg(Wb + 3);
    float w4  = __ldg(Wb + 4),  w5  = __ldg(Wb + 5),  w6  = __ldg(Wb + 6),  w7  = __ldg(Wb + 7);
    float w8  = __ldg(Wb + 8),  w9  = __ldg(Wb + 9),  w10 = __ldg(Wb + 10), w11 = __ldg(Wb + 11);
    float w12 = __ldg(Wb + 12), w13 = __ldg(Wb + 13), w14 = __ldg(Wb + 14), w15 = __ldg(Wb + 15);

    // ---- per-image params ----
    const float c0  = w0 * 6.0f;
    float hf = floorf(fminf(fmaxf(__fadd_rn(__fmul_rn(fabsf(w1), 8.0f), 2.0f), 2.0f), 12.0f));
    const int lo_ = 64 - (int)hf;
    const int hi_ = 64 + (int)hf;
    const float kx = w2 * (2.0f * PI_F / 128.0f);
    const float ky = w3 * (2.0f * PI_F / 128.0f);
    const float kd = w4 * (PI_F / 256.0f);
    const float a5 = w5 * 10.0f;
    const float off = truncf(w7 * 5.0f);
    const float bxf = 64.0f + off;                 // bx == by
    const float sigma = 4.0f + fabsf(w7) * 5.0f;
    const float ninv = -0.5f / (sigma * sigma);
    const float rw8 = w8 * 10.0f;
    const float cb = floorf(fminf(fmaxf(__fadd_rn(__fmul_rn(fabsf(w9), 8.0f), 2.0f), 2.0f), 16.0f));
    const float invcb = 1.0f / cb;
    const float angle = w10 * PI_F;
    float sa, ca;
    sincosf(angle, &sa, &ca);
    const float k11 = w11 * 4.0f;
    const float k12 = 0.2f * w12;
    const float k13 = 0.2f * w13;

    // ---- fill 1-D tables ----
    if (t < 128) {
        float tt = (float)t;
        s_sinx[t] = 0.5f * sinf(kx * tt);
        float db = tt - bxf;
        s_g1[t] = expf(db * db * ninv);
        int ip = (int)floorf((tt + 0.5f) * invcb);  // == floor(t/cb) for integer t, integer cb
        s_mi[t] = (ip & 1) ? 0.15f : -0.15f;        // -0.15 * p_i
        s_pr[t] = (ip & 1) ? -1.0f : 1.0f;          // p_j
        s_yacc[t] = 0.5f * sinf(ky * tt)
                  + 0.5f * sinf((tt + a5) * (PI_F / 128.0f))
                  + w6
                  - 0.5f * k13
                  + 0.15f;                           // checkerboard constant folded in
    }
    s_sind[t] = 0.5f * sinf(kd * (float)t);
    __syncthreads();

    // ---- per-thread j-quad constants ----
    const int j0 = (t & 31) * 4;
    const float dyf = (float)(j0 - 64);
    float yaccl[4], gyl[4], sqh[4], pjl[4];
#pragma unroll
    for (int l = 0; l < 4; ++l) {
        int jl = j0 + l;
        yaccl[l] = s_yacc[jl];
        gyl[l]  = s_g1[jl];
        pjl[l]  = s_pr[jl];
        sqh[l]  = (jl >= lo_ && jl < hi_) ? 0.5f : 0.0f;
    }

    const int r0 = t >> 5;                       // warp id = local row within 8-row group
    const int pg0 = ((base + r0) << 7) + j0;     // first global pixel for this thread
    float* op = out + gbase + pg0;

    const float SQRT10 = 3.16227766016838f;

    float mnv = __int_as_float(0x7f800000);
    float mxv = __int_as_float(0xff800000);

    // ---- pass 1: compute 64 rows into smem, fully cp.async-pipelined ----
#pragma unroll
    for (int k = 0; k < 8; ++k) {
        // wait for stage k (leave the newer in-flight group pending)
        if (k < 7) asm volatile("cp.async.wait_group 1;" ::: "memory");
        else       asm volatile("cp.async.wait_group 0;" ::: "memory");

        // consume my 16B of each stage buffer (theta lives in img block k)
        const float4 g4 = *(const float4*)&s_nbuf[k & 1][0][t4];
        const float4 u4 = *(const float4*)&s_nbuf[k & 1][1][t4];
        const float4 tc = *(const float4*)&img_s[(k << 10) + t4];

        // refill for stage k+2
        if (k < 6) {
            const int qn = (k + 2) << 10;
            cp16(&s_nbuf[k & 1][0][t4], ngc + qn + t4);
            cp16(&s_nbuf[k & 1][1][t4], nuc + qn + t4);
            cp16(&img_s[qn + t4],       thc + qn + t4);   // theta stage k+2 -> img block k+2
            CP_COMMIT();
        }

        const int i = base + r0 + (k << 3);      // global row
        const float dx = (float)i - 64.0f;
        const float dx2 = dx * dx;
        const float sinxi = s_sinx[i];
        const float g1i = s_g1[i];
        const float mi_i = s_mi[i];
        const float xm = (i >= lo_ && i < hi_) ? 1.0f : 0.0f;
        const float cadx = ca * dx;
        const int sb = i + j0;

        float gq[4] = {g4.x, g4.y, g4.z, g4.w};
        float uq[4] = {u4.x, u4.y, u4.z, u4.w};
        float thq[4] = {tc.x, tc.y, tc.z, tc.w};
        float v[4];
#pragma unroll
        for (int l = 0; l < 4; ++l) {
            const float dl = dyf + (float)l;
            float r = fast_sqrt(fmaf(dl, dl, dx2));
            float val = yaccl[l] + __saturatef(c0 - r);            // disk
            val = fmaf(xm, sqh[l], val);                           // central square
            val += sinxi;                                          // x-sinusoid
            val += s_sind[sb + l];                                 // diagonal sinusoid
            val = fmaf(g1i, gyl[l], val);                          // gaussian (separable)
            if (fabsf(r - rw8) < SQRT10) val += 1.0f;              // ring
            val = fmaf(mi_i, pjl[l], val);                         // checkerboard
            if (fabsf(fmaf(sa, dl, cadx)) < 3.0f) val += 0.6f;     // rotated line
            val = fmaf(0.5f, __sinf(thq[l] * k11), val);           // angular sinusoid
            val = fmaf(gq[l], k12, val);                           // gaussian noise
            val = fmaf(uq[l], k13, val);                           // uniform noise
            v[l] = val;
        }
        mnv = fminf(mnv, fminf(fminf(v[0], v[1]), fminf(v[2], v[3])));
        mxv = fmaxf(mxv, fmaxf(fmaxf(v[0], v[1]), fmaxf(v[2], v[3])));
        // overwrite this thread's own theta bytes with the computed pixels
        *(float4*)&img_s[(k << 10) + t4] = make_float4(v[0], v[1], v[2], v[3]);
    }

    // ---- local (half-image) min/max reduction ----
#pragma unroll
    for (int o = 16; o; o >>= 1) {
        mnv = fminf(mnv, __shfl_xor_sync(0xffffffffu, mnv, o));
        mxv = fmaxf(mxv, __shfl_xor_sync(0xffffffffu, mxv, o));
    }
    if ((t & 31) == 0) {
        s_red[t >> 5] = mnv;
        s_red[8 + (t >> 5)] = mxv;
    }
    __syncthreads();
    if (t == 0) {
        float gmn = s_red[0], gmx = s_red[8];
#pragma unroll
        for (int wdx = 1; wdx < 8; ++wdx) {
            gmn = fminf(gmn, s_red[wdx]);
            gmx = fmaxf(gmx, s_red[8 + wdx]);
        }
        s_red[16] = gmn;
        s_red[17] = gmx;
    }

    // ---- cluster exchange: combine halves ----
    CLUSTER_SYNC();   // release s_red[16..17] to peer; all cluster threads arrive
    if (t == 0) {
        unsigned int laddr = (unsigned int)__cvta_generic_to_shared(&s_red[16]);
        unsigned int paddr;
        unsigned int peer = (unsigned int)(rank ^ 1);
        asm("mapa.shared::cluster.u32 %0, %1, %2;" : "=r"(paddr) : "r"(laddr), "r"(peer));
        float pmn, pmx;
        asm("ld.shared::cluster.f32 %0, [%1];"   : "=f"(pmn) : "r"(paddr));
        asm("ld.shared::cluster.f32 %0, [%1+4];" : "=f"(pmx) : "r"(paddr));
        float gmn = fminf(s_red[16], pmn);
        float gmx = fmaxf(s_red[17], pmx);
        // fold contrast, inversion, min/max normalization into out = (x - x0) * A
        float c = 1.0f + w14;
        float pp = (w15 > 0.0f) ? -c : c;
        float ap = fabsf(pp);
        float denom = (gmx - gmn) + 1e-8f / ap;    // ap==0 -> inf -> A=0 -> out=0 (matches ref)
        float A = ((pp > 0.0f) ? 1.0f : -1.0f) / denom;
        float x0 = (pp > 0.0f) ? gmn : gmx;
        s_red[18] = A;
        s_red[19] = x0;
    }
    CLUSTER_SYNC();   // peer done reading our [16,17]; our threads see [18,19]

    const float A = s_red[18];
    const float C = -s_red[19] * A;

    // ---- pass 2: normalize from smem, store final ----
#pragma unroll 4
    for (int k = 0; k < 8; ++k) {
        const int q = k << 10;
        float4 vv = *(const float4*)&img_s[q + t4];
        vv.x = fmaf(vv.x, A, C);
        vv.y = fmaf(vv.y, A, C);
        vv.z = fmaf(vv.z, A, C);
        vv.w = fmaf(vv.w, A, C);
        *(float4*)(op + q) = vv;
    }
}

extern "C" void kernel_launch(void* const* d_in, const int* in_sizes, int n_in,
                              void* d_out, int out_size) {
    const float* W  = (const float*)d_in[0];   // (2048, 16)
    const float* ng = (const float*)d_in[1];   // (2048, 128, 128)
    const float* nu = (const float*)d_in[2];   // (2048, 128, 128)
    float* out = (float*)d_out;                // (2048, 1, 128, 128)

    (void)in_sizes; (void)n_in; (void)out_size;

    init_theta_kernel<<<NPIX / 256, 256>>>();
    decode_kernel<<<4096, 256>>>(W, ng, nu, out);
}